// round 3
// baseline (speedup 1.0000x reference)
#include <cuda_runtime.h>

#define BB 16
#define SS 2048
#define DD 64
#define TQ 8
#define NTHREADS 256
#define NWARPS (NTHREADS / 32)

// mask dtype flag: 0 = uint8 bool, 1 = int32, 2 = float32
__device__ int g_mask_kind;

__global__ void detect_mask_kind(const unsigned int* __restrict__ m)
{
    __shared__ int sawFloat, sawByte;
    if (threadIdx.x == 0) { sawFloat = 0; sawByte = 0; }
    __syncthreads();
    // scan first 4096 words (16KB) of the mask buffer
    for (int i = threadIdx.x; i < 4096; i += blockDim.x) {
        unsigned int w = m[i];
        if (w == 0x3F800000u)      sawFloat = 1;   // 1.0f pattern
        else if (w > 1u)           sawByte  = 1;   // packed uint8 bools
    }
    __syncthreads();
    if (threadIdx.x == 0)
        g_mask_kind = sawFloat ? 2 : (sawByte ? 0 : 1);
}

__global__ __launch_bounds__(NTHREADS) void sdpa_kernel(
    const float* __restrict__ q, const float* __restrict__ k,
    const float* __restrict__ v, const void* __restrict__ mask,
    float* __restrict__ out, float* __restrict__ attn)
{
    const int b  = blockIdx.y;
    const int q0 = blockIdx.x * TQ;
    const int tid = threadIdx.x;
    const int mk = g_mask_kind;

    extern __shared__ float smem[];
    float* sQ = smem;            // TQ*DD
    float* sS = smem + TQ * DD;  // TQ*SS score tile

    __shared__ float red[TQ][NWARPS];
    __shared__ float rowMax[TQ];
    __shared__ float rowInv[TQ];

    const float* qb = q + (size_t)b * SS * DD;
    const float* kb = k + (size_t)b * SS * DD;
    const float* vb = v + (size_t)b * SS * DD;
    const size_t mbase = (size_t)b * SS * SS + (size_t)q0 * SS;
    const unsigned char* m8  = (const unsigned char*)mask + mbase;
    const int*           m32 = (const int*)mask + mbase;
    const float*         mf  = (const float*)mask + mbase;

    // Load Q tile (8 rows x 64) into smem
    for (int i = tid; i < TQ * DD; i += NTHREADS)
        sQ[i] = qb[(size_t)q0 * DD + i];
    __syncthreads();

    // ---- Phase 1: scores + mask, track per-row running max ----
    float lmax[TQ];
#pragma unroll
    for (int r = 0; r < TQ; r++) lmax[r] = -3.4e38f;

    for (int j = tid; j < SS; j += NTHREADS) {
        float kr[DD];
        const float4* kp = (const float4*)(kb + (size_t)j * DD);
#pragma unroll
        for (int i = 0; i < DD / 4; i++) {
            float4 t = kp[i];
            kr[4*i+0] = t.x; kr[4*i+1] = t.y; kr[4*i+2] = t.z; kr[4*i+3] = t.w;
        }
#pragma unroll
        for (int r = 0; r < TQ; r++) {
            float acc = 0.f;
#pragma unroll
            for (int d2 = 0; d2 < DD; d2++)
                acc = fmaf(sQ[r*DD + d2], kr[d2], acc);
            acc *= 0.125f;                       // 1/sqrt(64)
            const size_t midx = (size_t)r * SS + j;
            bool masked;
            if (mk == 0)      masked = (m8[midx]  != 0);
            else if (mk == 1) masked = (m32[midx] != 0);
            else              masked = (mf[midx]  != 0.0f);
            if (masked) acc = -1e30f;
            sS[r*SS + j] = acc;
            lmax[r] = fmaxf(lmax[r], acc);
        }
    }

    // reduce row max: warp shuffle then cross-warp via smem
#pragma unroll
    for (int r = 0; r < TQ; r++) {
#pragma unroll
        for (int o = 16; o > 0; o >>= 1)
            lmax[r] = fmaxf(lmax[r], __shfl_xor_sync(0xffffffffu, lmax[r], o));
    }
    if ((tid & 31) == 0) {
#pragma unroll
        for (int r = 0; r < TQ; r++) red[r][tid >> 5] = lmax[r];
    }
    __syncthreads();
    if (tid < TQ) {
        float m = red[tid][0];
#pragma unroll
        for (int w = 1; w < NWARPS; w++) m = fmaxf(m, red[tid][w]);
        rowMax[tid] = m;
    }
    __syncthreads();

    // ---- Phase 2: exp + row sum (keep unnormalized p in smem) ----
    float rm[TQ];
#pragma unroll
    for (int r = 0; r < TQ; r++) rm[r] = rowMax[r];

    float lsum[TQ];
#pragma unroll
    for (int r = 0; r < TQ; r++) lsum[r] = 0.f;

    for (int j = tid; j < SS; j += NTHREADS) {
#pragma unroll
        for (int r = 0; r < TQ; r++) {
            float p = __expf(sS[r*SS + j] - rm[r]);
            sS[r*SS + j] = p;
            lsum[r] += p;
        }
    }
#pragma unroll
    for (int r = 0; r < TQ; r++) {
#pragma unroll
        for (int o = 16; o > 0; o >>= 1)
            lsum[r] += __shfl_xor_sync(0xffffffffu, lsum[r], o);
    }
    if ((tid & 31) == 0) {
#pragma unroll
        for (int r = 0; r < TQ; r++) red[r][tid >> 5] = lsum[r];
    }
    __syncthreads();
    if (tid < TQ) {
        float ssum = 0.f;
#pragma unroll
        for (int w = 0; w < NWARPS; w++) ssum += red[tid][w];
        rowInv[tid] = 1.0f / ssum;
    }
    __syncthreads();

    float inv[TQ];
#pragma unroll
    for (int r = 0; r < TQ; r++) inv[r] = rowInv[r];

    // ---- Phase 3: write normalized attention (coalesced over j) ----
    float* ab = attn + (size_t)b * SS * SS + (size_t)q0 * SS;
    for (int j = tid; j < SS; j += NTHREADS) {
#pragma unroll
        for (int r = 0; r < TQ; r++)
            ab[(size_t)r * SS + j] = sS[r*SS + j] * inv[r];
    }

    // ---- Phase 4: PV — thread owns (row rp, d) and (row rp+4, d) ----
    const int d  = tid & (DD - 1);
    const int rp = tid >> 6;   // 0..3
    float acc0 = 0.f, acc1 = 0.f;
#pragma unroll 4
    for (int j = 0; j < SS; j++) {
        float vv = vb[(size_t)j * DD + d];
        acc0 = fmaf(sS[rp*SS + j],       vv, acc0);
        acc1 = fmaf(sS[(rp+4)*SS + j],   vv, acc1);
    }
    float* ob = out + (size_t)b * SS * DD + (size_t)q0 * DD;
    ob[(size_t)rp       * DD + d] = acc0 * inv[rp];
    ob[(size_t)(rp + 4) * DD + d] = acc1 * inv[rp + 4];
}

extern "C" void kernel_launch(void* const* d_in, const int* in_sizes, int n_in,
                              void* d_out, int out_size)
{
    const float* q = (const float*)d_in[0];
    const float* k = (const float*)d_in[1];
    const float* v = (const float*)d_in[2];
    const void*  mask = d_in[3];

    float* out  = (float*)d_out;
    float* attn = out + (size_t)BB * SS * DD;   // tuple order: (output, attn)

    detect_mask_kind<<<1, 256>>>((const unsigned int*)mask);

    const int smem_bytes = (TQ * DD + TQ * SS) * sizeof(float);  // 67,584 B
    cudaFuncSetAttribute(sdpa_kernel,
                         cudaFuncAttributeMaxDynamicSharedMemorySize, smem_bytes);

    dim3 grid(SS / TQ, BB);
    sdpa_kernel<<<grid, NTHREADS, smem_bytes>>>(q, k, v, mask, out, attn);
}

// round 4
// speedup vs baseline: 3.7211x; 3.7211x over previous
#include <cuda_runtime.h>

#define BB 16
#define SS 2048
#define DD 64
#define TQ 32
#define NT 256
#define NQB (SS / TQ)
#define JTILE 128

// mask dtype flag: 0 = uint8 bool, 1 = int32, 2 = float32
__device__ int g_mask_kind;

__global__ void detect_mask_kind(const unsigned int* __restrict__ m)
{
    __shared__ int sawFloat, sawByte;
    if (threadIdx.x == 0) { sawFloat = 0; sawByte = 0; }
    __syncthreads();
    for (int i = threadIdx.x; i < 4096; i += blockDim.x) {
        unsigned int w = m[i];
        if (w == 0x3F800000u)      sawFloat = 1;   // 1.0f pattern
        else if (w > 1u)           sawByte  = 1;   // packed uint8 bools
    }
    __syncthreads();
    if (threadIdx.x == 0)
        g_mask_kind = sawFloat ? 2 : (sawByte ? 0 : 1);
}

__global__ __launch_bounds__(NT, 2) void sdpa_kernel(
    const float* __restrict__ q, const float* __restrict__ k,
    const float* __restrict__ v, const void* __restrict__ mask,
    float* __restrict__ out, float* __restrict__ attn)
{
    const int b   = blockIdx.y;
    const int q0  = blockIdx.x * TQ;
    const int tid = threadIdx.x;
    const int mk  = g_mask_kind;

    __shared__ float sQ[TQ * DD];     // 8 KB
    __shared__ float sInv[TQ];
    extern __shared__ float sDyn[];   // sP[TQ][JTILE] (16KB) + sV[JTILE][DD] (32KB)
    float* sP = sDyn;
    float* sV = sDyn + TQ * JTILE;

    const float* qb = q + ((size_t)b * SS + q0) * DD;
    const float* kb = k + (size_t)b * SS * DD;
    const float* vb = v + (size_t)b * SS * DD;
    float*       ab = attn + (size_t)b * SS * SS + (size_t)q0 * SS;

    const size_t mOff = (size_t)b * SS * SS + (size_t)q0 * SS;
    const unsigned char* m8  = (const unsigned char*)mask + mOff;
    const int*           m32 = (const int*)mask + mOff;
    const float*         mf  = (const float*)mask + mOff;

    // Q tile -> smem
    for (int i = tid; i < TQ * DD; i += NT) sQ[i] = qb[i];
    __syncthreads();

    // ================= Phase 1: scores -> exp -> raw p to gmem =================
    for (int jt = 0; jt < SS; jt += NT) {
        const int j = jt + tid;

        // pack mask column j for all 32 rows into a bitmap
        unsigned int mbits = 0;
        if (mk == 0) {
            #pragma unroll
            for (int r = 0; r < TQ; r++)
                mbits |= (m8[(size_t)r * SS + j] != 0 ? 1u : 0u) << r;
        } else if (mk == 1) {
            #pragma unroll
            for (int r = 0; r < TQ; r++)
                mbits |= (m32[(size_t)r * SS + j] != 0 ? 1u : 0u) << r;
        } else {
            #pragma unroll
            for (int r = 0; r < TQ; r++)
                mbits |= (mf[(size_t)r * SS + j] != 0.0f ? 1u : 0u) << r;
        }

        float acc[TQ];
        #pragma unroll
        for (int r = 0; r < TQ; r++) acc[r] = 0.f;

        const float4* kp = (const float4*)(kb + (size_t)j * DD);
        for (int c = 0; c < DD / 16; c++) {        // 4 chunks of 16 d
            float kr[16];
            #pragma unroll
            for (int i = 0; i < 4; i++) {
                float4 t = kp[c * 4 + i];
                kr[4*i]   = t.x; kr[4*i+1] = t.y;
                kr[4*i+2] = t.z; kr[4*i+3] = t.w;
            }
            const float* qc = sQ + c * 16;
            #pragma unroll
            for (int r = 0; r < TQ; r++) {
                const float* qr = qc + r * DD;     // uniform across warp -> LDS broadcast
                #pragma unroll
                for (int d = 0; d < 16; d++)
                    acc[r] = fmaf(qr[d], kr[d], acc[r]);
            }
        }

        #pragma unroll
        for (int r = 0; r < TQ; r++) {
            float p = ((mbits >> r) & 1u) ? 0.f : __expf(acc[r] * 0.125f);
            ab[(size_t)r * SS + j] = p;            // raw (unnormalized) p
        }
    }
    __syncthreads();   // all p visible block-wide (same SM, L1-coherent)

    // ================= Phase 2: row sums from just-written p =================
    {
        const int r = tid >> 3;        // 32 rows x 8 threads
        const int t = tid & 7;
        const float* row = ab + (size_t)r * SS;
        float s = 0.f;
        for (int j4 = t * 4; j4 < SS; j4 += 32) {
            float4 pv = *(const float4*)(row + j4);
            s += (pv.x + pv.y) + (pv.z + pv.w);
        }
        #pragma unroll
        for (int o = 4; o > 0; o >>= 1)
            s += __shfl_xor_sync(0xffffffffu, s, o);
        if (t == 0) sInv[r] = 1.0f / s;
    }
    __syncthreads();

    // ================= Phase 3: normalize attn + PV =================
    const int dp = (tid & 31) * 2;   // d pair (0..62)
    const int rg = tid >> 5;         // row group 0..7; rows rg, rg+8, rg+16, rg+24
    float a00=0,a01=0,a10=0,a11=0,a20=0,a21=0,a30=0,a31=0;

    for (int j0 = 0; j0 < SS; j0 += JTILE) {
        __syncthreads();
        // stage p tile: rescale, write back normalized attn, keep in smem
        #pragma unroll
        for (int t = 0; t < (TQ * JTILE) / (4 * NT); t++) {   // 4 iters
            int idx = t * NT + tid;        // 0..1023
            int r   = idx >> 5;            // 32 float4 per row
            int jj  = (idx & 31) * 4;
            float4 pv = *(const float4*)(ab + (size_t)r * SS + j0 + jj);
            float iv = sInv[r];
            pv.x *= iv; pv.y *= iv; pv.z *= iv; pv.w *= iv;
            *(float4*)(ab + (size_t)r * SS + j0 + jj) = pv;
            *(float4*)(sP + r * JTILE + jj) = pv;
        }
        // stage v tile
        #pragma unroll
        for (int t = 0; t < (JTILE * DD) / (4 * NT); t++) {   // 8 iters
            int idx = t * NT + tid;
            int jr  = idx >> 4;            // 16 float4 per row
            int dd  = (idx & 15) * 4;
            *(float4*)(sV + jr * DD + dd) =
                *(const float4*)(vb + (size_t)(j0 + jr) * DD + dd);
        }
        __syncthreads();

        for (int jj = 0; jj < JTILE; jj += 4) {
            float2 v0 = *(const float2*)(sV + (jj+0) * DD + dp);
            float2 v1 = *(const float2*)(sV + (jj+1) * DD + dp);
            float2 v2 = *(const float2*)(sV + (jj+2) * DD + dp);
            float2 v3 = *(const float2*)(sV + (jj+3) * DD + dp);

            float4 p0 = *(const float4*)(sP + (rg     ) * JTILE + jj);
            float4 p1 = *(const float4*)(sP + (rg +  8) * JTILE + jj);
            float4 p2 = *(const float4*)(sP + (rg + 16) * JTILE + jj);
            float4 p3 = *(const float4*)(sP + (rg + 24) * JTILE + jj);

            a00 = fmaf(p0.x, v0.x, a00); a01 = fmaf(p0.x, v0.y, a01);
            a00 = fmaf(p0.y, v1.x, a00); a01 = fmaf(p0.y, v1.y, a01);
            a00 = fmaf(p0.z, v2.x, a00); a01 = fmaf(p0.z, v2.y, a01);
            a00 = fmaf(p0.w, v3.x, a00); a01 = fmaf(p0.w, v3.y, a01);

            a10 = fmaf(p1.x, v0.x, a10); a11 = fmaf(p1.x, v0.y, a11);
            a10 = fmaf(p1.y, v1.x, a10); a11 = fmaf(p1.y, v1.y, a11);
            a10 = fmaf(p1.z, v2.x, a10); a11 = fmaf(p1.z, v2.y, a11);
            a10 = fmaf(p1.w, v3.x, a10); a11 = fmaf(p1.w, v3.y, a11);

            a20 = fmaf(p2.x, v0.x, a20); a21 = fmaf(p2.x, v0.y, a21);
            a20 = fmaf(p2.y, v1.x, a20); a21 = fmaf(p2.y, v1.y, a21);
            a20 = fmaf(p2.z, v2.x, a20); a21 = fmaf(p2.z, v2.y, a21);
            a20 = fmaf(p2.w, v3.x, a20); a21 = fmaf(p2.w, v3.y, a21);

            a30 = fmaf(p3.x, v0.x, a30); a31 = fmaf(p3.x, v0.y, a31);
            a30 = fmaf(p3.y, v1.x, a30); a31 = fmaf(p3.y, v1.y, a31);
            a30 = fmaf(p3.z, v2.x, a30); a31 = fmaf(p3.z, v2.y, a31);
            a30 = fmaf(p3.w, v3.x, a30); a31 = fmaf(p3.w, v3.y, a31);
        }
    }

    float* ob = out + ((size_t)b * SS + q0) * DD;
    *(float2*)(ob + (size_t)(rg     ) * DD + dp) = make_float2(a00, a01);
    *(float2*)(ob + (size_t)(rg +  8) * DD + dp) = make_float2(a10, a11);
    *(float2*)(ob + (size_t)(rg + 16) * DD + dp) = make_float2(a20, a21);
    *(float2*)(ob + (size_t)(rg + 24) * DD + dp) = make_float2(a30, a31);
}

extern "C" void kernel_launch(void* const* d_in, const int* in_sizes, int n_in,
                              void* d_out, int out_size)
{
    const float* q = (const float*)d_in[0];
    const float* k = (const float*)d_in[1];
    const float* v = (const float*)d_in[2];
    const void*  mask = d_in[3];

    float* out  = (float*)d_out;
    float* attn = out + (size_t)BB * SS * DD;   // tuple order: (output, attn)

    detect_mask_kind<<<1, 256>>>((const unsigned int*)mask);

    const int smem_bytes = (TQ * JTILE + JTILE * DD) * sizeof(float);  // 48 KB
    cudaFuncSetAttribute(sdpa_kernel,
                         cudaFuncAttributeMaxDynamicSharedMemorySize, smem_bytes);

    dim3 grid(NQB, BB);
    sdpa_kernel<<<grid, NT, smem_bytes>>>(q, k, v, mask, out, attn);
}

// round 5
// speedup vs baseline: 4.1683x; 1.1202x over previous
#include <cuda_runtime.h>

#define BB 16
#define SS 2048
#define DD 64
#define TQ 32
#define NT 256
#define KT 256      // phase-1 j tile
#define KP 68       // sK row pitch (floats): 68 % 32 == 4 -> conflict-free LDS.128
#define JT 128      // phase-3 j tile
#define PP 132      // sP row pitch
#define VP 68       // sV row pitch

// mask dtype flag: 0 = uint8 bool, 1 = int32, 2 = float32
__device__ int g_mask_kind;

__global__ void detect_mask_kind(const unsigned int* __restrict__ m)
{
    __shared__ int sawFloat, sawByte;
    if (threadIdx.x == 0) { sawFloat = 0; sawByte = 0; }
    __syncthreads();
    for (int i = threadIdx.x; i < 4096; i += blockDim.x) {
        unsigned int w = m[i];
        if (w == 0x3F800000u)      sawFloat = 1;   // 1.0f pattern
        else if (w > 1u)           sawByte  = 1;   // packed uint8 bools
    }
    __syncthreads();
    if (threadIdx.x == 0)
        g_mask_kind = sawFloat ? 2 : (sawByte ? 0 : 1);
}

__global__ __launch_bounds__(NT, 2) void sdpa_kernel(
    const float* __restrict__ q, const float* __restrict__ k,
    const float* __restrict__ v, const void* __restrict__ mask,
    float* __restrict__ out, float* __restrict__ attn)
{
    const int b   = blockIdx.y;
    const int q0  = blockIdx.x * TQ;
    const int tid = threadIdx.x;
    const int mk  = g_mask_kind;

    __shared__ float sQ[TQ * DD];      // 8 KB
    __shared__ float sInv[TQ];
    extern __shared__ float sDyn[];    // 69,632 B
    float* sK   = sDyn;                // [KT][KP]
    float* sP   = sDyn;                // [TQ][PP]   (phase 3)
    float* sV   = sDyn + TQ * PP;      // [JT][VP]   (phase 3)
    float* sRed = sDyn;                // [4][TQ][DD] (final reduce)

    const float* qb = q + ((size_t)b * SS + q0) * DD;
    const float* kb = k + (size_t)b * SS * DD;
    const float* vb = v + (size_t)b * SS * DD;
    float*       ab = attn + (size_t)b * SS * SS + (size_t)q0 * SS;

    const size_t mOff = (size_t)b * SS * SS + (size_t)q0 * SS;
    const unsigned char* m8  = (const unsigned char*)mask + mOff;
    const int*           m32 = (const int*)mask + mOff;
    const float*         mf  = (const float*)mask + mOff;

    // Q tile -> smem
    for (int i = tid; i < TQ * DD; i += NT) sQ[i] = qb[i];

    // ================= Phase 1: QK^T -> exp -> raw p to gmem =================
    const int tr = tid >> 5;   // warp id: rows tr, tr+8, tr+16, tr+24
    const int tc = tid & 31;   // cols tc + 32*jj

    float rsum[4] = {0.f, 0.f, 0.f, 0.f};

    for (int j0 = 0; j0 < SS; j0 += KT) {
        __syncthreads();
        // stage K tile [KT x DD] at pitch KP (LDG and STS both conflict-free)
        #pragma unroll
        for (int t = 0; t < (KT * DD) / (4 * NT); t++) {   // 16 iters
            int idx = t * NT + tid;
            int jr  = idx >> 4;
            int c4  = (idx & 15) << 2;
            *(float4*)(sK + jr * KP + c4) =
                *(const float4*)(kb + (size_t)(j0 + jr) * DD + c4);
        }
        __syncthreads();

        float acc[4][8];
        #pragma unroll
        for (int i = 0; i < 4; i++)
            #pragma unroll
            for (int jj = 0; jj < 8; jj++) acc[i][jj] = 0.f;

        #pragma unroll
        for (int c = 0; c < DD / 4; c++) {                 // 16 d-chunks
            float4 qf[4];
            #pragma unroll
            for (int i = 0; i < 4; i++)
                qf[i] = *(const float4*)(sQ + (tr + 8*i) * DD + 4*c);  // broadcast
            #pragma unroll
            for (int jj = 0; jj < 8; jj++) {
                float4 kf = *(const float4*)(sK + (tc + 32*jj) * KP + 4*c);
                #pragma unroll
                for (int i = 0; i < 4; i++)
                    acc[i][jj] = fmaf(qf[i].x, kf.x,
                                 fmaf(qf[i].y, kf.y,
                                 fmaf(qf[i].z, kf.z,
                                 fmaf(qf[i].w, kf.w, acc[i][jj]))));
            }
        }

        // epilogue: mask, exp, rowsum, store raw p
        #pragma unroll
        for (int i = 0; i < 4; i++) {
            const int r = tr + 8*i;
            #pragma unroll
            for (int jj = 0; jj < 8; jj++) {
                const int j = j0 + tc + 32*jj;
                const size_t mi = (size_t)r * SS + j;
                bool masked;
                if (mk == 0)      masked = (m8[mi]  != 0);
                else if (mk == 1) masked = (m32[mi] != 0);
                else              masked = (mf[mi]  != 0.0f);
                float p = masked ? 0.f : __expf(acc[i][jj] * 0.125f);
                rsum[i] += p;
                ab[mi] = p;
            }
        }
    }

    // per-warp rows are disjoint: shuffle-reduce, lane 0 writes 1/sum
    #pragma unroll
    for (int i = 0; i < 4; i++) {
        #pragma unroll
        for (int o = 16; o > 0; o >>= 1)
            rsum[i] += __shfl_xor_sync(0xffffffffu, rsum[i], o);
    }
    if (tc == 0) {
        #pragma unroll
        for (int i = 0; i < 4; i++) sInv[tr + 8*i] = 1.0f / rsum[i];
    }

    // ================= Phase 3: normalize attn + PV =================
    const int dg = tid & 7;          // d-group: d = dg*8 .. dg*8+7
    const int rg = (tid >> 3) & 7;   // rows rg*4 .. rg*4+3
    const int jq = tid >> 6;         // j-quarter within tile

    float oacc[4][8];
    #pragma unroll
    for (int ri = 0; ri < 4; ri++)
        #pragma unroll
        for (int dd = 0; dd < 8; dd++) oacc[ri][dd] = 0.f;

    for (int j0 = 0; j0 < SS; j0 += JT) {
        __syncthreads();
        // stage p: read raw, normalize, write back final attn, keep in smem
        #pragma unroll
        for (int t = 0; t < (TQ * JT) / (4 * NT); t++) {   // 4 iters
            int idx = t * NT + tid;
            int r   = idx >> 5;
            int j4  = (idx & 31) << 2;
            float4 pv = *(const float4*)(ab + (size_t)r * SS + j0 + j4);
            float iv = sInv[r];
            pv.x *= iv; pv.y *= iv; pv.z *= iv; pv.w *= iv;
            *(float4*)(ab + (size_t)r * SS + j0 + j4) = pv;
            *(float4*)(sP + r * PP + j4) = pv;
        }
        // stage V tile [JT x DD] at pitch VP
        #pragma unroll
        for (int t = 0; t < (JT * DD) / (4 * NT); t++) {   // 8 iters
            int idx = t * NT + tid;
            int jr  = idx >> 4;
            int c4  = (idx & 15) << 2;
            *(float4*)(sV + jr * VP + c4) =
                *(const float4*)(vb + (size_t)(j0 + jr) * DD + c4);
        }
        __syncthreads();

        #pragma unroll 2
        for (int jj = 0; jj < JT / 4; jj += 4) {
            const int jl = jq * (JT / 4) + jj;
            float4 pf[4];
            #pragma unroll
            for (int ri = 0; ri < 4; ri++)
                pf[ri] = *(const float4*)(sP + (rg*4 + ri) * PP + jl);

            float vv[4][8];
            #pragma unroll
            for (int t = 0; t < 4; t++) {
                float4 a = *(const float4*)(sV + (jl + t) * VP + dg*8);
                float4 c = *(const float4*)(sV + (jl + t) * VP + dg*8 + 4);
                vv[t][0]=a.x; vv[t][1]=a.y; vv[t][2]=a.z; vv[t][3]=a.w;
                vv[t][4]=c.x; vv[t][5]=c.y; vv[t][6]=c.z; vv[t][7]=c.w;
            }
            #pragma unroll
            for (int ri = 0; ri < 4; ri++)
                #pragma unroll
                for (int dd = 0; dd < 8; dd++)
                    oacc[ri][dd] = fmaf(pf[ri].x, vv[0][dd],
                                   fmaf(pf[ri].y, vv[1][dd],
                                   fmaf(pf[ri].z, vv[2][dd],
                                   fmaf(pf[ri].w, vv[3][dd], oacc[ri][dd]))));
        }
    }

    // reduce partial PV across the 4 j-quarters via smem
    __syncthreads();
    #pragma unroll
    for (int ri = 0; ri < 4; ri++)
        #pragma unroll
        for (int dd = 0; dd < 8; dd++)
            sRed[(jq * TQ + rg*4 + ri) * DD + dg*8 + dd] = oacc[ri][dd];
    __syncthreads();

    float* ob = out + ((size_t)b * SS + q0) * DD;
    #pragma unroll
    for (int t = 0; t < (TQ * DD) / NT; t++) {             // 8 iters
        int o   = t * NT + tid;
        int row = o >> 6;
        int d   = o & 63;
        float s = sRed[(0 * TQ + row) * DD + d]
                + sRed[(1 * TQ + row) * DD + d]
                + sRed[(2 * TQ + row) * DD + d]
                + sRed[(3 * TQ + row) * DD + d];
        ob[(size_t)row * DD + d] = s;
    }
}

extern "C" void kernel_launch(void* const* d_in, const int* in_sizes, int n_in,
                              void* d_out, int out_size)
{
    const float* q = (const float*)d_in[0];
    const float* k = (const float*)d_in[1];
    const float* v = (const float*)d_in[2];
    const void*  mask = d_in[3];

    float* out  = (float*)d_out;
    float* attn = out + (size_t)BB * SS * DD;   // tuple order: (output, attn)

    detect_mask_kind<<<1, 256>>>((const unsigned int*)mask);

    const int smem_bytes = KT * KP * sizeof(float);  // 69,632 B (phase-1 dominates)
    cudaFuncSetAttribute(sdpa_kernel,
                         cudaFuncAttributeMaxDynamicSharedMemorySize, smem_bytes);

    dim3 grid(SS / TQ, BB);
    sdpa_kernel<<<grid, NT, smem_bytes>>>(q, k, v, mask, out, attn);
}

// round 9
// speedup vs baseline: 5.2570x; 1.2612x over previous
#include <cuda_runtime.h>
#include <cuda_bf16.h>
#include <cstdint>

#define BB 16
#define SS 2048
#define DD 64
#define TQ 128
#define NJ 128
#define NT 256
#define NTILES (SS / NJ)

// dynamic smem offsets (from 1024-aligned base)
#define OQH 0
#define OQL 16384
#define OKH 32768
#define OKL 49152
#define OVH 65536
#define OVL 81920
#define OMB 98304
#define SMEM_DYN (98304 + 2048 + 1024)

__device__ int g_mask_kind;
__device__ float g_inv[BB * SS];

#define SWZ(o) ((o) ^ (((o) >> 3) & 0x70u))

static __device__ __forceinline__ uint32_t packbf(float lo, float hi) {
    uint32_t r;
    asm("cvt.rn.bf16x2.f32 %0, %1, %2;" : "=r"(r) : "f"(hi), "f"(lo));
    return r;
}
static __device__ __forceinline__ float ubf(uint32_t u) { return __uint_as_float(u); }

static __device__ __forceinline__ void ldsm4(uint32_t* r, uint32_t a) {
    asm volatile("ldmatrix.sync.aligned.m8n8.x4.shared.b16 {%0,%1,%2,%3}, [%4];"
        : "=r"(r[0]), "=r"(r[1]), "=r"(r[2]), "=r"(r[3]) : "r"(a));
}
static __device__ __forceinline__ void ldsm4t(uint32_t* r, uint32_t a) {
    asm volatile("ldmatrix.sync.aligned.m8n8.x4.trans.shared.b16 {%0,%1,%2,%3}, [%4];"
        : "=r"(r[0]), "=r"(r[1]), "=r"(r[2]), "=r"(r[3]) : "r"(a));
}
static __device__ __forceinline__ void mma16816(float* c, const uint32_t* a,
                                                uint32_t b0, uint32_t b1) {
    asm volatile("mma.sync.aligned.m16n8k16.row.col.f32.bf16.bf16.f32 "
        "{%0,%1,%2,%3}, {%4,%5,%6,%7}, {%8,%9}, {%0,%1,%2,%3};"
        : "+f"(c[0]), "+f"(c[1]), "+f"(c[2]), "+f"(c[3])
        : "r"(a[0]), "r"(a[1]), "r"(a[2]), "r"(a[3]), "r"(b0), "r"(b1));
}

static __device__ __forceinline__ uint32_t s2u(const void* p) {
    uint32_t a;
    asm("{ .reg .u64 t; cvta.to.shared.u64 t, %1; cvt.u32.u64 %0, t; }" : "=r"(a) : "l"(p));
    return a;
}

__global__ void detect_mask_kind(const unsigned int* __restrict__ m)
{
    __shared__ int sawFloat, sawByte;
    if (threadIdx.x == 0) { sawFloat = 0; sawByte = 0; }
    __syncthreads();
    for (int i = threadIdx.x; i < 4096; i += blockDim.x) {
        unsigned int w = m[i];
        if (w == 0x3F800000u) sawFloat = 1;
        else if (w > 1u)      sawByte = 1;
    }
    __syncthreads();
    if (threadIdx.x == 0)
        g_mask_kind = sawFloat ? 2 : (sawByte ? 0 : 1);
}

static __device__ __forceinline__ uint32_t b2b(uint32_t wv, int sh) {
    uint32_t r = 0;
    r |= ((wv & 0x000000FFu) ? 1u : 0u) << sh;
    r |= ((wv & 0x0000FF00u) ? 1u : 0u) << (sh + 1);
    r |= ((wv & 0x00FF0000u) ? 1u : 0u) << (sh + 2);
    r |= ((wv & 0xFF000000u) ? 1u : 0u) << (sh + 3);
    return r;
}

// stage a [128 x 64] fp32 tile as bf16 hi/lo into SW128 smem (128B rows)
static __device__ __forceinline__ void stage_bf(const float* __restrict__ g,
                                                char* sh, char* sl, float sc, int tid)
{
    for (int i = tid; i < 1024; i += NT) {
        int row = i >> 3, c8 = (i & 7) << 3;
        float4 a = *(const float4*)(g + row * 64 + c8);
        float4 b = *(const float4*)(g + row * 64 + c8 + 4);
        float y[8] = {a.x*sc, a.y*sc, a.z*sc, a.w*sc, b.x*sc, b.y*sc, b.z*sc, b.w*sc};
        uint32_t h[4], l[4];
#pragma unroll
        for (int p = 0; p < 4; p++) {
            h[p] = packbf(y[2*p], y[2*p+1]);
            float f0 = ubf(h[p] << 16), f1 = ubf(h[p] & 0xFFFF0000u);
            l[p] = packbf(y[2*p] - f0, y[2*p+1] - f1);
        }
        uint32_t off = SWZ((uint32_t)(row * 128 + c8 * 2));
        *(uint4*)(sh + off) = make_uint4(h[0], h[1], h[2], h[3]);
        *(uint4*)(sl + off) = make_uint4(l[0], l[1], l[2], l[3]);
    }
}

__global__ __launch_bounds__(NT) void sdpa_mma_kernel(
    const float* __restrict__ q, const float* __restrict__ k,
    const float* __restrict__ v, const void* __restrict__ maskp,
    float* __restrict__ out, float* __restrict__ attn)
{
    const int b   = blockIdx.y;
    const int q0  = blockIdx.x * TQ;
    const int tid = threadIdx.x;
    const int w   = tid >> 5;
    const int lid = tid & 31;
    const int g   = lid >> 2;
    const int t2  = lid & 3;
    const int mk  = g_mask_kind;
    const int bq  = b * SS + q0;

    extern __shared__ char dsm_raw[];
    char* dsm = (char*)(((uintptr_t)dsm_raw + 1023) & ~(uintptr_t)1023);
    uint32_t* sMB = (uint32_t*)(dsm + OMB);

    const uint32_t uQH = s2u(dsm + OQH), uQL = s2u(dsm + OQL);
    const uint32_t uKH = s2u(dsm + OKH), uKL = s2u(dsm + OKL);
    const uint32_t uVH = s2u(dsm + OVH), uVL = s2u(dsm + OVL);

    const float* qb = q + ((size_t)bq) * DD;
    const float* kb = k + (size_t)b * SS * DD;
    const float* vb = v + (size_t)b * SS * DD;
    const unsigned char* m8b  = (const unsigned char*)maskp + (size_t)b * SS * SS;
    const uint32_t*      m32b = (const uint32_t*)maskp + (size_t)b * SS * SS;

    // ldmatrix lane address patterns
    const int krow = (lid & 7) + ((lid >> 4) & 1) * 8;   // K (non-trans B): 16-23,24-31 -> +8 rows
    const int kbyt = ((lid >> 3) & 1) * 16;              //                  8-15,24-31 -> +16B
    const int qrow = (lid & 7) + ((lid >> 3) & 1) * 8;   // Q (A) / V (trans B)
    const int qbyt = ((lid >> 4) & 1) * 16;

    // Q staged once, pre-scaled by 1/sqrt(64)
    stage_bf(qb, dsm + OQH, dsm + OQL, 0.125f, tid);

    float OD[8][4];
#pragma unroll
    for (int i = 0; i < 8; i++)
#pragma unroll
        for (int jx = 0; jx < 4; jx++) OD[i][jx] = 0.f;

    float rs0 = 0.f, rs1 = 0.f;

    for (int t = 0; t < NTILES; t++) {
        const int j0 = t * NJ;
        __syncthreads();   // prior tile's GEMM2 done reading sV

        stage_bf(kb + (size_t)j0 * DD, dsm + OKH, dsm + OKL, 1.0f, tid);
        stage_bf(vb + (size_t)j0 * DD, dsm + OVH, dsm + OVL, 1.0f, tid);

        // mask bitmap: sMB[row][0..3], 128 rows x 128 bits
        for (int u = tid; u < 512; u += NT) {
            int row = u >> 2, wi = u & 3;
            uint32_t bits = 0;
            if (mk == 0) {
                const uint4* pp = (const uint4*)(m8b + (size_t)(q0 + row) * SS + j0 + wi * 32);
                uint4 x = pp[0], y = pp[1];
                bits = b2b(x.x, 0)  | b2b(x.y, 4)  | b2b(x.z, 8)  | b2b(x.w, 12)
                     | b2b(y.x, 16) | b2b(y.y, 20) | b2b(y.z, 24) | b2b(y.w, 28);
            } else {
                const uint4* pp = (const uint4*)(m32b + (size_t)(q0 + row) * SS + j0 + wi * 32);
#pragma unroll
                for (int i = 0; i < 8; i++) {
                    uint4 x = pp[i];
                    bits |= (x.x ? 1u : 0u) << (i*4)     | (x.y ? 1u : 0u) << (i*4+1)
                          | (x.z ? 1u : 0u) << (i*4+2)   | (x.w ? 1u : 0u) << (i*4+3);
                }
            }
            sMB[row * 4 + wi] = bits;
        }
        __syncthreads();

        // ---------------- GEMM1: C[16][4] = Q(16q) x K^T(128j), 3-term split ----------------
        float C[16][4];
#pragma unroll
        for (int fn = 0; fn < 16; fn++)
#pragma unroll
            for (int jx = 0; jx < 4; jx++) C[fn][jx] = 0.f;

#pragma unroll
        for (int ks = 0; ks < 4; ks++) {
            uint32_t qh[4], ql[4];
            uint32_t qoff = (uint32_t)(w * 2048 +
                (((qrow * 128) | (ks * 32) | qbyt) ^ ((qrow & 7) << 4)));
            ldsm4(qh, uQH + qoff);
            ldsm4(ql, uQL + qoff);
#pragma unroll
            for (int jg = 0; jg < 8; jg++) {
                uint32_t kh[4], kl[4];
                uint32_t koff = (uint32_t)(jg * 2048 +
                    (((krow * 128) | (ks * 32) | kbyt) ^ ((krow & 7) << 4)));
                ldsm4(kh, uKH + koff);
                ldsm4(kl, uKL + koff);
                mma16816(C[2*jg],   qh, kh[0], kh[1]);
                mma16816(C[2*jg+1], qh, kh[2], kh[3]);
                mma16816(C[2*jg],   qh, kl[0], kl[1]);
                mma16816(C[2*jg+1], qh, kl[2], kl[3]);
                mma16816(C[2*jg],   ql, kh[0], kh[1]);
                mma16816(C[2*jg+1], ql, kh[2], kh[3]);
            }
        }

        // ---------------- epilogue: mask, exp, rowsum, raw attn, C->P frags ----------------
        uint32_t mw0[4], mw1[4];
#pragma unroll
        for (int i = 0; i < 4; i++) {
            mw0[i] = sMB[(w * 16 + g) * 4 + i];
            mw1[i] = sMB[(w * 16 + 8 + g) * 4 + i];
        }
        float* ar0 = attn + ((size_t)(bq + w * 16 + g)) * SS + j0;
        float* ar1 = ar0 + (size_t)8 * SS;

        uint32_t phi[8][4], plo[8][4];
#pragma unroll
        for (int fn = 0; fn < 16; fn++) {
            int sh = (fn & 3) * 8 + t2 * 2;
            uint32_t w0 = mw0[fn >> 2], w1 = mw1[fn >> 2];
            float p0 = ((w0 >> sh) & 1u)       ? 0.f : __expf(C[fn][0]);
            float p1 = ((w0 >> (sh + 1)) & 1u) ? 0.f : __expf(C[fn][1]);
            float p2 = ((w1 >> sh) & 1u)       ? 0.f : __expf(C[fn][2]);
            float p3 = ((w1 >> (sh + 1)) & 1u) ? 0.f : __expf(C[fn][3]);
            rs0 += p0 + p1;
            rs1 += p2 + p3;
            *(float2*)(ar0 + fn * 8 + t2 * 2) = make_float2(p0, p1);
            *(float2*)(ar1 + fn * 8 + t2 * 2) = make_float2(p2, p3);

            uint32_t h01 = packbf(p0, p1), h23 = packbf(p2, p3);
            float f0 = ubf(h01 << 16), f1 = ubf(h01 & 0xFFFF0000u);
            float f2 = ubf(h23 << 16), f3 = ubf(h23 & 0xFFFF0000u);
            uint32_t l01 = packbf(p0 - f0, p1 - f1);
            uint32_t l23 = packbf(p2 - f2, p3 - f3);
            int k2 = fn >> 1, o = (fn & 1) * 2;
            phi[k2][o] = h01; phi[k2][o + 1] = h23;
            plo[k2][o] = l01; plo[k2][o + 1] = l23;
        }

        // ---------------- GEMM2: OD += P(16q x 128j) x V(128j x 64d), 3-term ----------------
#pragma unroll
        for (int ks2 = 0; ks2 < 8; ks2++) {
#pragma unroll
            for (int dg = 0; dg < 4; dg++) {
                uint32_t vh[4], vl[4];
                uint32_t voff = (uint32_t)(ks2 * 2048 +
                    (((qrow * 128) | (dg * 32) | qbyt) ^ ((qrow & 7) << 4)));
                ldsm4t(vh, uVH + voff);
                ldsm4t(vl, uVL + voff);
                mma16816(OD[2*dg],   phi[ks2], vh[0], vh[1]);
                mma16816(OD[2*dg+1], phi[ks2], vh[2], vh[3]);
                mma16816(OD[2*dg],   phi[ks2], vl[0], vl[1]);
                mma16816(OD[2*dg+1], phi[ks2], vl[2], vl[3]);
                mma16816(OD[2*dg],   plo[ks2], vh[0], vh[1]);
                mma16816(OD[2*dg+1], plo[ks2], vh[2], vh[3]);
            }
        }
    }

    // row sums: quad-reduce (lanes g*4+t2 share rows)
    rs0 += __shfl_xor_sync(0xffffffffu, rs0, 1);
    rs0 += __shfl_xor_sync(0xffffffffu, rs0, 2);
    rs1 += __shfl_xor_sync(0xffffffffu, rs1, 1);
    rs1 += __shfl_xor_sync(0xffffffffu, rs1, 2);
    float inv0 = 1.0f / rs0, inv1 = 1.0f / rs1;
    if (t2 == 0) {
        g_inv[bq + w * 16 + g]     = inv0;
        g_inv[bq + w * 16 + 8 + g] = inv1;
    }

    float* o0 = out + (size_t)(bq + w * 16 + g) * DD;
    float* o1 = o0 + (size_t)8 * DD;
#pragma unroll
    for (int dn = 0; dn < 8; dn++) {
        *(float2*)(o0 + dn * 8 + t2 * 2) = make_float2(OD[dn][0] * inv0, OD[dn][1] * inv0);
        *(float2*)(o1 + dn * 8 + t2 * 2) = make_float2(OD[dn][2] * inv1, OD[dn][3] * inv1);
    }
}

__global__ __launch_bounds__(256) void normalize_attn(float* __restrict__ attn)
{
    size_t i4 = (size_t)blockIdx.x * 256 + threadIdx.x;   // 16,777,216 float4s
    int row = (int)(i4 >> 9);
    float inv = g_inv[row];
    float4* p = (float4*)attn + i4;
    float4 pv = *p;
    pv.x *= inv; pv.y *= inv; pv.z *= inv; pv.w *= inv;
    *p = pv;
}

extern "C" void kernel_launch(void* const* d_in, const int* in_sizes, int n_in,
                              void* d_out, int out_size)
{
    const float* q = (const float*)d_in[0];
    const float* k = (const float*)d_in[1];
    const float* v = (const float*)d_in[2];
    const void*  mask = d_in[3];

    float* out  = (float*)d_out;
    float* attn = out + (size_t)BB * SS * DD;   // tuple order: (output, attn)

    detect_mask_kind<<<1, 256>>>((const unsigned int*)mask);

    cudaFuncSetAttribute(sdpa_mma_kernel,
                         cudaFuncAttributeMaxDynamicSharedMemorySize, SMEM_DYN);

    dim3 grid(SS / TQ, BB);
    sdpa_mma_kernel<<<grid, NT, SMEM_DYN>>>(q, k, v, mask, out, attn);

    normalize_attn<<<(BB * (size_t)SS * SS / 4) / 256, 256>>>(attn);
}